// round 10
// baseline (speedup 1.0000x reference)
#include <cuda_runtime.h>
#include <cuda_fp16.h>
#include <cstdint>

#define NN 50000
#define NE 800000
#define D  256
#define BN_EPS 1e-5f
#define NSCB 196   // ceil(NN/256) scan blocks

// ---------------- scratch (static device allocations) ----------------
__device__ __half g_h[NN * D];       // 25.6 MB: h = x @ W^T in fp16
__device__ float g_dinv[NN];
__device__ int   g_cnt[NN];
__device__ int   g_off[NN + 1];      // local-exclusive offsets (pre-boff)
__device__ int   g_src[NE];
__device__ int   g_bsum[NSCB];
__device__ int   g_boff[NSCB];       // published by k_fill block 0
__device__ float g_bnstat[2 * D];
__device__ float g_bn_a[D];
__device__ float g_bn_b[D];

// ---------------- multi-block scan helper ----------------
__device__ __forceinline__ int block_incl_scan256(int v, int tid) {
    __shared__ int ws[8];
    int lane = tid & 31, w = tid >> 5;
    int inc = v;
#pragma unroll
    for (int o = 1; o < 32; o <<= 1) {
        int n = __shfl_up_sync(0xFFFFFFFFu, inc, o);
        if (lane >= o) inc += n;
    }
    if (lane == 31) ws[w] = inc;
    __syncthreads();
    if (w == 0) {
        int s = (lane < 8) ? ws[lane] : 0;
#pragma unroll
        for (int o = 1; o < 8; o <<= 1) {
            int n = __shfl_up_sync(0xFFFFFFFFu, s, o);
            if (lane >= o) s += n;
        }
        if (lane < 8) ws[lane] = s;
    }
    __syncthreads();
    return inc + (w > 0 ? ws[w - 1] : 0);
}

// ---------------- GEMM (+fused edge count): H(fp16) = X @ W^T ----------------
#define GPAD 20
#define EPB 512

__device__ __forceinline__ unsigned pack_bf16x2(float k0, float k1) {
    unsigned r;
    asm("cvt.rn.bf16x2.f32 %0, %1, %2;" : "=r"(r) : "f"(k1), "f"(k0));
    return r;
}

#define MMA_BF16(acc, a, b) \
    asm volatile("mma.sync.aligned.m16n8k16.row.col.f32.bf16.bf16.f32 " \
                 "{%0,%1,%2,%3},{%4,%5,%6,%7},{%8,%9},{%0,%1,%2,%3};" \
                 : "+f"(acc[0]), "+f"(acc[1]), "+f"(acc[2]), "+f"(acc[3]) \
                 : "r"(a[0]), "r"(a[1]), "r"(a[2]), "r"(a[3]), "r"(b[0]), "r"(b[1]))

#define LDSM4(r, addr) \
    asm volatile("ldmatrix.sync.aligned.m8n8.x4.shared.b16 {%0,%1,%2,%3}, [%4];" \
                 : "=r"(r[0]), "=r"(r[1]), "=r"(r[2]), "=r"(r[3]) : "r"(addr))

__device__ __forceinline__ void split2(float a, float b, unsigned& hi, unsigned& lo) {
    hi = __byte_perm(__float_as_uint(a), __float_as_uint(b), 0x7632);
    float la = a - __uint_as_float(hi << 16);
    float lb = b - __uint_as_float(hi & 0xFFFF0000u);
    lo = pack_bf16x2(la, lb);
}

__global__ __launch_bounds__(256) void k_gemm_bf16(const float* __restrict__ X,
                                                   const float* __restrict__ W,
                                                   __half* __restrict__ H,
                                                   const int* __restrict__ ei) {
    // fused edge-degree count: this block's slice
    {
        int bid = blockIdx.y * gridDim.x + blockIdx.x;
        int e0 = bid * EPB;
#pragma unroll
        for (int p = 0; p < 2; p++) {
            int e = e0 + threadIdx.x + p * 256;
            if (e < NE && e < e0 + EPB) atomicAdd(&g_cnt[ei[NE + e]], 1);
        }
    }

    __shared__ unsigned Ahi[128][GPAD], Alo[128][GPAD];
    __shared__ unsigned Bhi[64][GPAD],  Blo[64][GPAD];

    const int bm = blockIdx.x * 128;
    const int bn = blockIdx.y * 64;
    const int tid = threadIdx.x;
    const int warp = tid >> 5, lane = tid & 31;
    const int wm = warp & 3, wn = warp >> 2;
    const int grp = lane >> 2, tig = lane & 3;

    const int lr = lane & 7, sel = lane >> 3;
    const int a_row = ((sel & 1) ? 8 : 0) + lr;
    const int a_col = (sel & 2) ? 4 : 0;
    const int b_row = ((sel & 2) ? 8 : 0) + lr;
    const int b_col = (sel & 1) ? 4 : 0;

    const uint32_t sAhi = (uint32_t)__cvta_generic_to_shared(&Ahi[0][0]);
    const uint32_t sAlo = (uint32_t)__cvta_generic_to_shared(&Alo[0][0]);
    const uint32_t sBhi = (uint32_t)__cvta_generic_to_shared(&Bhi[0][0]);
    const uint32_t sBlo = (uint32_t)__cvta_generic_to_shared(&Blo[0][0]);

    float acc[2][4][4];
#pragma unroll
    for (int mi = 0; mi < 2; mi++)
#pragma unroll
        for (int ni = 0; ni < 4; ni++)
#pragma unroll
            for (int q = 0; q < 4; q++) acc[mi][ni][q] = 0.0f;

    for (int k0 = 0; k0 < D; k0 += 32) {
#pragma unroll
        for (int p = 0; p < 4; p++) {
            int f = tid + p * 256;
            int row = f >> 3;
            int q = f & 7;
            float4 v = make_float4(0.f, 0.f, 0.f, 0.f);
            int gr = bm + row;
            if (gr < NN) v = *(const float4*)&X[(size_t)gr * D + k0 + q * 4];
            unsigned h0, l0, h1, l1;
            split2(v.x, v.y, h0, l0);
            split2(v.z, v.w, h1, l1);
            Ahi[row][q * 2]     = h0;
            Ahi[row][q * 2 + 1] = h1;
            Alo[row][q * 2]     = l0;
            Alo[row][q * 2 + 1] = l1;
        }
#pragma unroll
        for (int p = 0; p < 2; p++) {
            int f = tid + p * 256;
            int row = f >> 3;
            int q = f & 7;
            float4 v = *(const float4*)&W[(size_t)(bn + row) * D + k0 + q * 4];
            unsigned h0, l0, h1, l1;
            split2(v.x, v.y, h0, l0);
            split2(v.z, v.w, h1, l1);
            Bhi[row][q * 2]     = h0;
            Bhi[row][q * 2 + 1] = h1;
            Blo[row][q * 2]     = l0;
            Blo[row][q * 2 + 1] = l1;
        }
        __syncthreads();

#pragma unroll
        for (int ks = 0; ks < 16; ks += 8) {
            unsigned ah[2][4], al[2][4], bh[2][4], bl[2][4];
#pragma unroll
            for (int mi = 0; mi < 2; mi++) {
                uint32_t off = (uint32_t)(((wm * 32 + mi * 16 + a_row) * GPAD + ks + a_col) << 2);
                LDSM4(ah[mi], sAhi + off);
                LDSM4(al[mi], sAlo + off);
            }
#pragma unroll
            for (int p = 0; p < 2; p++) {
                uint32_t off = (uint32_t)(((wn * 32 + p * 16 + b_row) * GPAD + ks + b_col) << 2);
                LDSM4(bh[p], sBhi + off);
                LDSM4(bl[p], sBlo + off);
            }
#pragma unroll
            for (int mi = 0; mi < 2; mi++)
#pragma unroll
                for (int ni = 0; ni < 4; ni++) {
                    int p = ni >> 1, o = (ni & 1) * 2;
                    MMA_BF16(acc[mi][ni], ah[mi], (&bh[p][o]));
                    MMA_BF16(acc[mi][ni], ah[mi], (&bl[p][o]));
                    MMA_BF16(acc[mi][ni], al[mi], (&bh[p][o]));
                }
        }
        __syncthreads();
    }

#pragma unroll
    for (int mi = 0; mi < 2; mi++)
#pragma unroll
        for (int ni = 0; ni < 4; ni++) {
            int r0 = bm + wm * 32 + mi * 16 + grp;
            int c0 = bn + wn * 32 + ni * 8 + tig * 2;
            if (r0 < NN)
                *(__half2*)&H[(size_t)r0 * D + c0] = __floats2half2_rn(acc[mi][ni][0], acc[mi][ni][1]);
            if (r0 + 8 < NN)
                *(__half2*)&H[(size_t)(r0 + 8) * D + c0] = __floats2half2_rn(acc[mi][ni][2], acc[mi][ni][3]);
        }
}

// ---------------- scan phase 1 + dinv ----------------
__global__ __launch_bounds__(256) void k_scan1(void) {
    int tid = threadIdx.x;
    int idx = blockIdx.x * 256 + tid;
    int v = (idx < NN) ? g_cnt[idx] : 0;
    if (idx < NN) g_dinv[idx] = rsqrtf((float)(v + 1));
    int inc = block_incl_scan256(v, tid);
    if (idx < NN) g_off[idx] = inc - v;
    if (tid == 255) g_bsum[blockIdx.x] = inc;
}

// ---------------- fill CSR (inline block-sum scan; publishes g_boff) ----------------
__global__ __launch_bounds__(256) void k_fill(const int* __restrict__ ei) {
    __shared__ int sboff[NSCB];
    int t = threadIdx.x;
    {
        int v = (t < NSCB) ? g_bsum[t] : 0;
        int inc = block_incl_scan256(v, t);
        if (t < NSCB) {
            sboff[t] = inc - v;
            if (blockIdx.x == 0) g_boff[t] = inc - v;
        }
    }
    __syncthreads();
    int e = blockIdx.x * 256 + t;
    if (e < NE) {
        int r = ei[e];
        int c = ei[NE + e];
        int pos = g_off[c] + sboff[c >> 8] + atomicSub(&g_cnt[c], 1) - 1;
        g_src[pos] = r;
    }
}

// ---------------- fused gather + bias + BN-stats (128 thr, prefetched) ----------------
// thread d handles column pair (2d, 2d+1); grid-stride over nodes.
__global__ __launch_bounds__(128) void k_gather_bn(const float* __restrict__ bias,
                                                   float* __restrict__ out) {
    const int d = threadIdx.x;
    const __half2* __restrict__ H2 = (const __half2*)g_h;
    const float2 bi = *(const float2*)&bias[2 * d];
    float s0 = 0.f, s1 = 0.f, q0 = 0.f, q1 = 0.f;

    for (int c = blockIdx.x; c < NN; c += gridDim.x) {
        const float dc = g_dinv[c];
        const int beg = g_off[c] + g_boff[c >> 8];
        const int end = (c + 1 < NN) ? g_off[c + 1] + g_boff[(c + 1) >> 8] : NE;

        float2 hs = __half22float2(H2[(size_t)c * 128 + d]);
        float a0 = hs.x * dc, a1 = hs.y * dc;   // self loop

        int n4 = (end - beg) & ~3;
        int jend4 = beg + n4;
        int j = beg;
        if (j < jend4) {
            // prime: group-0 indices + weights
            int r0 = __ldg(&g_src[j]);
            int r1 = __ldg(&g_src[j + 1]);
            int r2 = __ldg(&g_src[j + 2]);
            int r3 = __ldg(&g_src[j + 3]);
            float w0 = __ldg(&g_dinv[r0]), w1 = __ldg(&g_dinv[r1]);
            float w2 = __ldg(&g_dinv[r2]), w3 = __ldg(&g_dinv[r3]);
            while (true) {
                int nj = j + 4;
                bool more = nj < jend4;
                int t0, t1, t2, t3;
                float x0, x1, x2, x3;
                if (more) {  // prefetch next group's indices+weights
                    t0 = __ldg(&g_src[nj]);
                    t1 = __ldg(&g_src[nj + 1]);
                    t2 = __ldg(&g_src[nj + 2]);
                    t3 = __ldg(&g_src[nj + 3]);
                    x0 = __ldg(&g_dinv[t0]); x1 = __ldg(&g_dinv[t1]);
                    x2 = __ldg(&g_dinv[t2]); x3 = __ldg(&g_dinv[t3]);
                }
                float2 v0 = __half22float2(H2[(size_t)r0 * 128 + d]);
                float2 v1 = __half22float2(H2[(size_t)r1 * 128 + d]);
                float2 v2 = __half22float2(H2[(size_t)r2 * 128 + d]);
                float2 v3 = __half22float2(H2[(size_t)r3 * 128 + d]);
                a0 = fmaf(v0.x, w0, a0); a1 = fmaf(v0.y, w0, a1);
                a0 = fmaf(v1.x, w1, a0); a1 = fmaf(v1.y, w1, a1);
                a0 = fmaf(v2.x, w2, a0); a1 = fmaf(v2.y, w2, a1);
                a0 = fmaf(v3.x, w3, a0); a1 = fmaf(v3.y, w3, a1);
                if (!more) { j = nj; break; }
                r0 = t0; r1 = t1; r2 = t2; r3 = t3;
                w0 = x0; w1 = x1; w2 = x2; w3 = x3;
                j = nj;
            }
        }
        for (; j < end; j++) {
            int r = __ldg(&g_src[j]);
            float w = __ldg(&g_dinv[r]);
            float2 v = __half22float2(H2[(size_t)r * 128 + d]);
            a0 = fmaf(v.x, w, a0); a1 = fmaf(v.y, w, a1);
        }
        float o0 = fmaf(a0, dc, bi.x);
        float o1 = fmaf(a1, dc, bi.y);
        *(float2*)&out[(size_t)c * D + 2 * d] = make_float2(o0, o1);
        s0 += o0; s1 += o1;
        q0 = fmaf(o0, o0, q0); q1 = fmaf(o1, o1, q1);
    }
    atomicAdd(&g_bnstat[2 * d], s0);
    atomicAdd(&g_bnstat[2 * d + 1], s1);
    atomicAdd(&g_bnstat[D + 2 * d], q0);
    atomicAdd(&g_bnstat[D + 2 * d + 1], q1);
}

// ---------------- BN finalize ----------------
__global__ void k_bn_params(const float* __restrict__ gamma, const float* __restrict__ beta) {
    int d = threadIdx.x;
    float inv_n = 1.0f / (float)NN;
    float mean = g_bnstat[d] * inv_n;
    float var = g_bnstat[D + d] * inv_n - mean * mean;
    float a = gamma[d] * rsqrtf(var + BN_EPS);
    g_bn_a[d] = a;
    g_bn_b[d] = beta[d] - mean * a;
}

__global__ void k_bn_apply(float* __restrict__ out) {
    int idx = blockIdx.x * blockDim.x + threadIdx.x;
    if (idx >= NN * (D / 4)) return;
    int dq = (idx & 63) * 4;
    float4 a = *(const float4*)&g_bn_a[dq];
    float4 b = *(const float4*)&g_bn_b[dq];
    float4 v = ((const float4*)out)[idx];
    float4 o;
    o.x = fmaxf(fmaf(v.x, a.x, b.x), 0.f);
    o.y = fmaxf(fmaf(v.y, a.y, b.y), 0.f);
    o.z = fmaxf(fmaf(v.z, a.z, b.z), 0.f);
    o.w = fmaxf(fmaf(v.w, a.w, b.w), 0.f);
    ((float4*)out)[idx] = o;
}

// ---------------- launch ----------------
extern "C" void kernel_launch(void* const* d_in, const int* in_sizes, int n_in,
                              void* d_out, int out_size) {
    const float* x = (const float*)d_in[0];
    const int* ei = (const int*)d_in[1];
    const float* W = (const float*)d_in[2];
    const float* bias = (const float*)d_in[3];
    const float* gamma = (const float*)d_in[4];
    const float* beta = (const float*)d_in[5];
    float* out = (float*)d_out;

    __half* h;  cudaGetSymbolAddress((void**)&h, g_h);
    int* cnt;   cudaGetSymbolAddress((void**)&cnt, g_cnt);
    float* bns; cudaGetSymbolAddress((void**)&bns, g_bnstat);

    cudaMemsetAsync(cnt, 0, NN * sizeof(int));
    cudaMemsetAsync(bns, 0, 2 * D * sizeof(float));

    // 1: gemm (+edge count)   2: scan1   3: fill (+boff)   4: gather (profiled)
    dim3 ggrid((NN + 127) / 128, D / 64);
    k_gemm_bf16<<<ggrid, 256>>>(x, W, h, ei);

    k_scan1<<<NSCB, 256>>>();
    k_fill<<<(NE + 255) / 256, 256>>>(ei);

    k_gather_bn<<<1480, 128>>>(bias, out);

    k_bn_params<<<1, 256>>>(gamma, beta);

    int q = NN * (D / 4);
    k_bn_apply<<<(q + 255) / 256, 256>>>(out);
}

// round 11
// speedup vs baseline: 1.5548x; 1.5548x over previous
#include <cuda_runtime.h>
#include <cuda_fp16.h>
#include <cstdint>

#define NN 50000
#define NE 800000
#define D  256
#define BN_EPS 1e-5f
#define NSCB 196   // ceil(NN/256) scan blocks

// ---------------- scratch (static device allocations) ----------------
__device__ __half g_h[NN * D];       // 25.6 MB: h = x @ W^T in fp16
__device__ float g_dinv[NN];
__device__ int   g_cnt[NN];
__device__ int   g_off[NN + 1];      // local-exclusive offsets (pre-boff)
__device__ int   g_src[NE];
__device__ int   g_bsum[NSCB];
__device__ int   g_boff[NSCB];       // published by k_fill block 0
__device__ float g_bnstat[2 * D];
__device__ float g_bn_a[D];
__device__ float g_bn_b[D];

// ---------------- multi-block scan helper ----------------
__device__ __forceinline__ int block_incl_scan256(int v, int tid) {
    __shared__ int ws[8];
    int lane = tid & 31, w = tid >> 5;
    int inc = v;
#pragma unroll
    for (int o = 1; o < 32; o <<= 1) {
        int n = __shfl_up_sync(0xFFFFFFFFu, inc, o);
        if (lane >= o) inc += n;
    }
    if (lane == 31) ws[w] = inc;
    __syncthreads();
    if (w == 0) {
        int s = (lane < 8) ? ws[lane] : 0;
#pragma unroll
        for (int o = 1; o < 8; o <<= 1) {
            int n = __shfl_up_sync(0xFFFFFFFFu, s, o);
            if (lane >= o) s += n;
        }
        if (lane < 8) ws[lane] = s;
    }
    __syncthreads();
    return inc + (w > 0 ? ws[w - 1] : 0);
}

// ---------------- GEMM (+fused edge count): H(fp16) = X @ W^T ----------------
#define GPAD 20
#define EPB 512

__device__ __forceinline__ unsigned pack_bf16x2(float k0, float k1) {
    unsigned r;
    asm("cvt.rn.bf16x2.f32 %0, %1, %2;" : "=r"(r) : "f"(k1), "f"(k0));
    return r;
}

#define MMA_BF16(acc, a, b) \
    asm volatile("mma.sync.aligned.m16n8k16.row.col.f32.bf16.bf16.f32 " \
                 "{%0,%1,%2,%3},{%4,%5,%6,%7},{%8,%9},{%0,%1,%2,%3};" \
                 : "+f"(acc[0]), "+f"(acc[1]), "+f"(acc[2]), "+f"(acc[3]) \
                 : "r"(a[0]), "r"(a[1]), "r"(a[2]), "r"(a[3]), "r"(b[0]), "r"(b[1]))

#define LDSM4(r, addr) \
    asm volatile("ldmatrix.sync.aligned.m8n8.x4.shared.b16 {%0,%1,%2,%3}, [%4];" \
                 : "=r"(r[0]), "=r"(r[1]), "=r"(r[2]), "=r"(r[3]) : "r"(addr))

__device__ __forceinline__ void split2(float a, float b, unsigned& hi, unsigned& lo) {
    hi = __byte_perm(__float_as_uint(a), __float_as_uint(b), 0x7632);
    float la = a - __uint_as_float(hi << 16);
    float lb = b - __uint_as_float(hi & 0xFFFF0000u);
    lo = pack_bf16x2(la, lb);
}

__global__ __launch_bounds__(256) void k_gemm_bf16(const float* __restrict__ X,
                                                   const float* __restrict__ W,
                                                   __half* __restrict__ H,
                                                   const int* __restrict__ ei) {
    // fused edge-degree count: this block's slice
    {
        int bid = blockIdx.y * gridDim.x + blockIdx.x;
        int e0 = bid * EPB;
#pragma unroll
        for (int p = 0; p < 2; p++) {
            int e = e0 + threadIdx.x + p * 256;
            if (e < NE && e < e0 + EPB) atomicAdd(&g_cnt[ei[NE + e]], 1);
        }
    }

    __shared__ unsigned Ahi[128][GPAD], Alo[128][GPAD];
    __shared__ unsigned Bhi[64][GPAD],  Blo[64][GPAD];

    const int bm = blockIdx.x * 128;
    const int bn = blockIdx.y * 64;
    const int tid = threadIdx.x;
    const int warp = tid >> 5, lane = tid & 31;
    const int wm = warp & 3, wn = warp >> 2;
    const int grp = lane >> 2, tig = lane & 3;

    const int lr = lane & 7, sel = lane >> 3;
    const int a_row = ((sel & 1) ? 8 : 0) + lr;
    const int a_col = (sel & 2) ? 4 : 0;
    const int b_row = ((sel & 2) ? 8 : 0) + lr;
    const int b_col = (sel & 1) ? 4 : 0;

    const uint32_t sAhi = (uint32_t)__cvta_generic_to_shared(&Ahi[0][0]);
    const uint32_t sAlo = (uint32_t)__cvta_generic_to_shared(&Alo[0][0]);
    const uint32_t sBhi = (uint32_t)__cvta_generic_to_shared(&Bhi[0][0]);
    const uint32_t sBlo = (uint32_t)__cvta_generic_to_shared(&Blo[0][0]);

    float acc[2][4][4];
#pragma unroll
    for (int mi = 0; mi < 2; mi++)
#pragma unroll
        for (int ni = 0; ni < 4; ni++)
#pragma unroll
            for (int q = 0; q < 4; q++) acc[mi][ni][q] = 0.0f;

    for (int k0 = 0; k0 < D; k0 += 32) {
#pragma unroll
        for (int p = 0; p < 4; p++) {
            int f = tid + p * 256;
            int row = f >> 3;
            int q = f & 7;
            float4 v = make_float4(0.f, 0.f, 0.f, 0.f);
            int gr = bm + row;
            if (gr < NN) v = *(const float4*)&X[(size_t)gr * D + k0 + q * 4];
            unsigned h0, l0, h1, l1;
            split2(v.x, v.y, h0, l0);
            split2(v.z, v.w, h1, l1);
            Ahi[row][q * 2]     = h0;
            Ahi[row][q * 2 + 1] = h1;
            Alo[row][q * 2]     = l0;
            Alo[row][q * 2 + 1] = l1;
        }
#pragma unroll
        for (int p = 0; p < 2; p++) {
            int f = tid + p * 256;
            int row = f >> 3;
            int q = f & 7;
            float4 v = *(const float4*)&W[(size_t)(bn + row) * D + k0 + q * 4];
            unsigned h0, l0, h1, l1;
            split2(v.x, v.y, h0, l0);
            split2(v.z, v.w, h1, l1);
            Bhi[row][q * 2]     = h0;
            Bhi[row][q * 2 + 1] = h1;
            Blo[row][q * 2]     = l0;
            Blo[row][q * 2 + 1] = l1;
        }
        __syncthreads();

#pragma unroll
        for (int ks = 0; ks < 16; ks += 8) {
            unsigned ah[2][4], al[2][4], bh[2][4], bl[2][4];
#pragma unroll
            for (int mi = 0; mi < 2; mi++) {
                uint32_t off = (uint32_t)(((wm * 32 + mi * 16 + a_row) * GPAD + ks + a_col) << 2);
                LDSM4(ah[mi], sAhi + off);
                LDSM4(al[mi], sAlo + off);
            }
#pragma unroll
            for (int p = 0; p < 2; p++) {
                uint32_t off = (uint32_t)(((wn * 32 + p * 16 + b_row) * GPAD + ks + b_col) << 2);
                LDSM4(bh[p], sBhi + off);
                LDSM4(bl[p], sBlo + off);
            }
#pragma unroll
            for (int mi = 0; mi < 2; mi++)
#pragma unroll
                for (int ni = 0; ni < 4; ni++) {
                    int p = ni >> 1, o = (ni & 1) * 2;
                    MMA_BF16(acc[mi][ni], ah[mi], (&bh[p][o]));
                    MMA_BF16(acc[mi][ni], ah[mi], (&bl[p][o]));
                    MMA_BF16(acc[mi][ni], al[mi], (&bh[p][o]));
                }
        }
        __syncthreads();
    }

#pragma unroll
    for (int mi = 0; mi < 2; mi++)
#pragma unroll
        for (int ni = 0; ni < 4; ni++) {
            int r0 = bm + wm * 32 + mi * 16 + grp;
            int c0 = bn + wn * 32 + ni * 8 + tig * 2;
            if (r0 < NN)
                *(__half2*)&H[(size_t)r0 * D + c0] = __floats2half2_rn(acc[mi][ni][0], acc[mi][ni][1]);
            if (r0 + 8 < NN)
                *(__half2*)&H[(size_t)(r0 + 8) * D + c0] = __floats2half2_rn(acc[mi][ni][2], acc[mi][ni][3]);
        }
}

// ---------------- scan phase 1 + dinv ----------------
__global__ __launch_bounds__(256) void k_scan1(void) {
    int tid = threadIdx.x;
    int idx = blockIdx.x * 256 + tid;
    int v = (idx < NN) ? g_cnt[idx] : 0;
    if (idx < NN) g_dinv[idx] = rsqrtf((float)(v + 1));
    int inc = block_incl_scan256(v, tid);
    if (idx < NN) g_off[idx] = inc - v;
    if (tid == 255) g_bsum[blockIdx.x] = inc;
}

// ---------------- fill CSR (inline block-sum scan; publishes g_boff) ----------------
__global__ __launch_bounds__(256) void k_fill(const int* __restrict__ ei) {
    __shared__ int sboff[NSCB];
    int t = threadIdx.x;
    {
        int v = (t < NSCB) ? g_bsum[t] : 0;
        int inc = block_incl_scan256(v, t);
        if (t < NSCB) {
            sboff[t] = inc - v;
            if (blockIdx.x == 0) g_boff[t] = inc - v;
        }
    }
    __syncthreads();
    int e = blockIdx.x * 256 + t;
    if (e < NE) {
        int r = ei[e];
        int c = ei[NE + e];
        int pos = g_off[c] + sboff[c >> 8] + atomicSub(&g_cnt[c], 1) - 1;
        g_src[pos] = r;
    }
}

// ---------------- fused gather + bias + BN-stats (smem-staged) ----------------
// 128 threads; thread d owns column pair (2d,2d+1). Per node: stage (src, dinv[src])
// pairs in smem cooperatively, then all threads sweep the staged list.
__global__ __launch_bounds__(128) void k_gather_bn(const float* __restrict__ bias,
                                                   float* __restrict__ out) {
    __shared__ int   sidx[128];
    __shared__ float sw[128];
    const int d = threadIdx.x;
    const __half2* __restrict__ H2 = (const __half2*)g_h;
    const float2 bi = *(const float2*)&bias[2 * d];
    float s0 = 0.f, s1 = 0.f, q0 = 0.f, q1 = 0.f;

    for (int c = blockIdx.x; c < NN; c += gridDim.x) {
        const float dc = g_dinv[c];
        const int beg = g_off[c] + g_boff[c >> 8];
        const int end = (c + 1 < NN) ? g_off[c + 1] + g_boff[(c + 1) >> 8] : NE;

        float2 hs = __half22float2(__ldg(H2 + (((unsigned)c << 7) + d)));
        float a0 = hs.x * dc, a1 = hs.y * dc;   // self loop

        for (int base = beg; base < end; base += 128) {
            int n = end - base;
            if (n > 128) n = 128;
            if (d < n) {
                int r = __ldg(&g_src[base + d]);
                sidx[d] = r;
                sw[d] = __ldg(&g_dinv[r]);
            }
            __syncthreads();
            int k = 0;
            for (; k + 3 < n; k += 4) {
                int r0 = sidx[k],     r1 = sidx[k + 1];
                int r2 = sidx[k + 2], r3 = sidx[k + 3];
                float w0 = sw[k],     w1 = sw[k + 1];
                float w2 = sw[k + 2], w3 = sw[k + 3];
                float2 v0 = __half22float2(__ldg(H2 + (((unsigned)r0 << 7) + d)));
                float2 v1 = __half22float2(__ldg(H2 + (((unsigned)r1 << 7) + d)));
                float2 v2 = __half22float2(__ldg(H2 + (((unsigned)r2 << 7) + d)));
                float2 v3 = __half22float2(__ldg(H2 + (((unsigned)r3 << 7) + d)));
                a0 = fmaf(v0.x, w0, a0); a1 = fmaf(v0.y, w0, a1);
                a0 = fmaf(v1.x, w1, a0); a1 = fmaf(v1.y, w1, a1);
                a0 = fmaf(v2.x, w2, a0); a1 = fmaf(v2.y, w2, a1);
                a0 = fmaf(v3.x, w3, a0); a1 = fmaf(v3.y, w3, a1);
            }
            for (; k < n; k++) {
                int r = sidx[k];
                float w = sw[k];
                float2 v = __half22float2(__ldg(H2 + (((unsigned)r << 7) + d)));
                a0 = fmaf(v.x, w, a0); a1 = fmaf(v.y, w, a1);
            }
            __syncthreads();
        }
        float o0 = fmaf(a0, dc, bi.x);
        float o1 = fmaf(a1, dc, bi.y);
        *(float2*)&out[(size_t)c * D + 2 * d] = make_float2(o0, o1);
        s0 += o0; s1 += o1;
        q0 = fmaf(o0, o0, q0); q1 = fmaf(o1, o1, q1);
    }
    atomicAdd(&g_bnstat[2 * d], s0);
    atomicAdd(&g_bnstat[2 * d + 1], s1);
    atomicAdd(&g_bnstat[D + 2 * d], q0);
    atomicAdd(&g_bnstat[D + 2 * d + 1], q1);
}

// ---------------- BN finalize ----------------
__global__ void k_bn_params(const float* __restrict__ gamma, const float* __restrict__ beta) {
    int d = threadIdx.x;
    float inv_n = 1.0f / (float)NN;
    float mean = g_bnstat[d] * inv_n;
    float var = g_bnstat[D + d] * inv_n - mean * mean;
    float a = gamma[d] * rsqrtf(var + BN_EPS);
    g_bn_a[d] = a;
    g_bn_b[d] = beta[d] - mean * a;
}

__global__ void k_bn_apply(float* __restrict__ out) {
    int idx = blockIdx.x * blockDim.x + threadIdx.x;
    if (idx >= NN * (D / 4)) return;
    int dq = (idx & 63) * 4;
    float4 a = *(const float4*)&g_bn_a[dq];
    float4 b = *(const float4*)&g_bn_b[dq];
    float4 v = ((const float4*)out)[idx];
    float4 o;
    o.x = fmaxf(fmaf(v.x, a.x, b.x), 0.f);
    o.y = fmaxf(fmaf(v.y, a.y, b.y), 0.f);
    o.z = fmaxf(fmaf(v.z, a.z, b.z), 0.f);
    o.w = fmaxf(fmaf(v.w, a.w, b.w), 0.f);
    ((float4*)out)[idx] = o;
}

// ---------------- launch ----------------
extern "C" void kernel_launch(void* const* d_in, const int* in_sizes, int n_in,
                              void* d_out, int out_size) {
    const float* x = (const float*)d_in[0];
    const int* ei = (const int*)d_in[1];
    const float* W = (const float*)d_in[2];
    const float* bias = (const float*)d_in[3];
    const float* gamma = (const float*)d_in[4];
    const float* beta = (const float*)d_in[5];
    float* out = (float*)d_out;

    __half* h;  cudaGetSymbolAddress((void**)&h, g_h);
    int* cnt;   cudaGetSymbolAddress((void**)&cnt, g_cnt);
    float* bns; cudaGetSymbolAddress((void**)&bns, g_bnstat);

    cudaMemsetAsync(cnt, 0, NN * sizeof(int));
    cudaMemsetAsync(bns, 0, 2 * D * sizeof(float));

    // 1: gemm (+edge count)   2: scan1   3: fill (+boff)   4: gather (profiled)
    dim3 ggrid((NN + 127) / 128, D / 64);
    k_gemm_bf16<<<ggrid, 256>>>(x, W, h, ei);

    k_scan1<<<NSCB, 256>>>();
    k_fill<<<(NE + 255) / 256, 256>>>(ei);

    k_gather_bn<<<1480, 128>>>(bias, out);

    k_bn_params<<<1, 256>>>(gamma, beta);

    int q = NN * (D / 4);
    k_bn_apply<<<(q + 255) / 256, 256>>>(out);
}

// round 12
// speedup vs baseline: 1.6153x; 1.0389x over previous
#include <cuda_runtime.h>
#include <cuda_fp16.h>
#include <cstdint>

#define NN 50000
#define NE 800000
#define D  256
#define BN_EPS 1e-5f
#define NSCB 196   // ceil(NN/256) scan blocks

// ---------------- scratch (static device allocations) ----------------
__device__ __half g_h[NN * D];       // 25.6 MB: h (later scaled to h*dinv in k_fill)
__device__ float g_dinv[NN];
__device__ int   g_cnt[NN];
__device__ int   g_off[NN + 1];      // local-exclusive offsets (pre-boff)
__device__ int   g_src[NE];
__device__ int   g_bsum[NSCB];
__device__ int   g_boff[NSCB];       // published by k_fill block 0
__device__ float g_bnstat[2 * D];
__device__ float g_bn_a[D];
__device__ float g_bn_b[D];

// ---------------- multi-block scan helper ----------------
__device__ __forceinline__ int block_incl_scan256(int v, int tid) {
    __shared__ int ws[8];
    int lane = tid & 31, w = tid >> 5;
    int inc = v;
#pragma unroll
    for (int o = 1; o < 32; o <<= 1) {
        int n = __shfl_up_sync(0xFFFFFFFFu, inc, o);
        if (lane >= o) inc += n;
    }
    if (lane == 31) ws[w] = inc;
    __syncthreads();
    if (w == 0) {
        int s = (lane < 8) ? ws[lane] : 0;
#pragma unroll
        for (int o = 1; o < 8; o <<= 1) {
            int n = __shfl_up_sync(0xFFFFFFFFu, s, o);
            if (lane >= o) s += n;
        }
        if (lane < 8) ws[lane] = s;
    }
    __syncthreads();
    return inc + (w > 0 ? ws[w - 1] : 0);
}

// ---------------- GEMM (+fused edge count): H(fp16) = X @ W^T ----------------
#define GPAD 20
#define EPB 512

__device__ __forceinline__ unsigned pack_bf16x2(float k0, float k1) {
    unsigned r;
    asm("cvt.rn.bf16x2.f32 %0, %1, %2;" : "=r"(r) : "f"(k1), "f"(k0));
    return r;
}

#define MMA_BF16(acc, a, b) \
    asm volatile("mma.sync.aligned.m16n8k16.row.col.f32.bf16.bf16.f32 " \
                 "{%0,%1,%2,%3},{%4,%5,%6,%7},{%8,%9},{%0,%1,%2,%3};" \
                 : "+f"(acc[0]), "+f"(acc[1]), "+f"(acc[2]), "+f"(acc[3]) \
                 : "r"(a[0]), "r"(a[1]), "r"(a[2]), "r"(a[3]), "r"(b[0]), "r"(b[1]))

#define LDSM4(r, addr) \
    asm volatile("ldmatrix.sync.aligned.m8n8.x4.shared.b16 {%0,%1,%2,%3}, [%4];" \
                 : "=r"(r[0]), "=r"(r[1]), "=r"(r[2]), "=r"(r[3]) : "r"(addr))

__device__ __forceinline__ void split2(float a, float b, unsigned& hi, unsigned& lo) {
    hi = __byte_perm(__float_as_uint(a), __float_as_uint(b), 0x7632);
    float la = a - __uint_as_float(hi << 16);
    float lb = b - __uint_as_float(hi & 0xFFFF0000u);
    lo = pack_bf16x2(la, lb);
}

__global__ __launch_bounds__(256) void k_gemm_bf16(const float* __restrict__ X,
                                                   const float* __restrict__ W,
                                                   __half* __restrict__ H,
                                                   const int* __restrict__ ei) {
    // fused edge-degree count: this block's slice
    {
        int bid = blockIdx.y * gridDim.x + blockIdx.x;
        int e0 = bid * EPB;
#pragma unroll
        for (int p = 0; p < 2; p++) {
            int e = e0 + threadIdx.x + p * 256;
            if (e < NE && e < e0 + EPB) atomicAdd(&g_cnt[ei[NE + e]], 1);
        }
    }

    __shared__ unsigned Ahi[128][GPAD], Alo[128][GPAD];
    __shared__ unsigned Bhi[64][GPAD],  Blo[64][GPAD];

    const int bm = blockIdx.x * 128;
    const int bn = blockIdx.y * 64;
    const int tid = threadIdx.x;
    const int warp = tid >> 5, lane = tid & 31;
    const int wm = warp & 3, wn = warp >> 2;
    const int grp = lane >> 2, tig = lane & 3;

    const int lr = lane & 7, sel = lane >> 3;
    const int a_row = ((sel & 1) ? 8 : 0) + lr;
    const int a_col = (sel & 2) ? 4 : 0;
    const int b_row = ((sel & 2) ? 8 : 0) + lr;
    const int b_col = (sel & 1) ? 4 : 0;

    const uint32_t sAhi = (uint32_t)__cvta_generic_to_shared(&Ahi[0][0]);
    const uint32_t sAlo = (uint32_t)__cvta_generic_to_shared(&Alo[0][0]);
    const uint32_t sBhi = (uint32_t)__cvta_generic_to_shared(&Bhi[0][0]);
    const uint32_t sBlo = (uint32_t)__cvta_generic_to_shared(&Blo[0][0]);

    float acc[2][4][4];
#pragma unroll
    for (int mi = 0; mi < 2; mi++)
#pragma unroll
        for (int ni = 0; ni < 4; ni++)
#pragma unroll
            for (int q = 0; q < 4; q++) acc[mi][ni][q] = 0.0f;

    for (int k0 = 0; k0 < D; k0 += 32) {
#pragma unroll
        for (int p = 0; p < 4; p++) {
            int f = tid + p * 256;
            int row = f >> 3;
            int q = f & 7;
            float4 v = make_float4(0.f, 0.f, 0.f, 0.f);
            int gr = bm + row;
            if (gr < NN) v = *(const float4*)&X[(size_t)gr * D + k0 + q * 4];
            unsigned h0, l0, h1, l1;
            split2(v.x, v.y, h0, l0);
            split2(v.z, v.w, h1, l1);
            Ahi[row][q * 2]     = h0;
            Ahi[row][q * 2 + 1] = h1;
            Alo[row][q * 2]     = l0;
            Alo[row][q * 2 + 1] = l1;
        }
#pragma unroll
        for (int p = 0; p < 2; p++) {
            int f = tid + p * 256;
            int row = f >> 3;
            int q = f & 7;
            float4 v = *(const float4*)&W[(size_t)(bn + row) * D + k0 + q * 4];
            unsigned h0, l0, h1, l1;
            split2(v.x, v.y, h0, l0);
            split2(v.z, v.w, h1, l1);
            Bhi[row][q * 2]     = h0;
            Bhi[row][q * 2 + 1] = h1;
            Blo[row][q * 2]     = l0;
            Blo[row][q * 2 + 1] = l1;
        }
        __syncthreads();

#pragma unroll
        for (int ks = 0; ks < 16; ks += 8) {
            unsigned ah[2][4], al[2][4], bh[2][4], bl[2][4];
#pragma unroll
            for (int mi = 0; mi < 2; mi++) {
                uint32_t off = (uint32_t)(((wm * 32 + mi * 16 + a_row) * GPAD + ks + a_col) << 2);
                LDSM4(ah[mi], sAhi + off);
                LDSM4(al[mi], sAlo + off);
            }
#pragma unroll
            for (int p = 0; p < 2; p++) {
                uint32_t off = (uint32_t)(((wn * 32 + p * 16 + b_row) * GPAD + ks + b_col) << 2);
                LDSM4(bh[p], sBhi + off);
                LDSM4(bl[p], sBlo + off);
            }
#pragma unroll
            for (int mi = 0; mi < 2; mi++)
#pragma unroll
                for (int ni = 0; ni < 4; ni++) {
                    int p = ni >> 1, o = (ni & 1) * 2;
                    MMA_BF16(acc[mi][ni], ah[mi], (&bh[p][o]));
                    MMA_BF16(acc[mi][ni], ah[mi], (&bl[p][o]));
                    MMA_BF16(acc[mi][ni], al[mi], (&bh[p][o]));
                }
        }
        __syncthreads();
    }

#pragma unroll
    for (int mi = 0; mi < 2; mi++)
#pragma unroll
        for (int ni = 0; ni < 4; ni++) {
            int r0 = bm + wm * 32 + mi * 16 + grp;
            int c0 = bn + wn * 32 + ni * 8 + tig * 2;
            if (r0 < NN)
                *(__half2*)&H[(size_t)r0 * D + c0] = __floats2half2_rn(acc[mi][ni][0], acc[mi][ni][1]);
            if (r0 + 8 < NN)
                *(__half2*)&H[(size_t)(r0 + 8) * D + c0] = __floats2half2_rn(acc[mi][ni][2], acc[mi][ni][3]);
        }
}

// ---------------- scan phase 1 + dinv ----------------
__global__ __launch_bounds__(256) void k_scan1(void) {
    int tid = threadIdx.x;
    int idx = blockIdx.x * 256 + tid;
    int v = (idx < NN) ? g_cnt[idx] : 0;
    if (idx < NN) g_dinv[idx] = rsqrtf((float)(v + 1));
    int inc = block_incl_scan256(v, tid);
    if (idx < NN) g_off[idx] = inc - v;
    if (tid == 255) g_bsum[blockIdx.x] = inc;
}

// ---------------- fill CSR (+inline block scan, +h *= dinv scaling) ----------------
// grid = 3125 blocks; block b also scales h rows [16b, 16b+16).
__global__ __launch_bounds__(256) void k_fill(const int* __restrict__ ei) {
    __shared__ int sboff[NSCB];
    int t = threadIdx.x;
    {
        int v = (t < NSCB) ? g_bsum[t] : 0;
        int inc = block_incl_scan256(v, t);
        if (t < NSCB) {
            sboff[t] = inc - v;
            if (blockIdx.x == 0) g_boff[t] = inc - v;
        }
    }
    __syncthreads();
    int e = blockIdx.x * 256 + t;
    if (e < NE) {
        int r = ei[e];
        int c = ei[NE + e];
        int pos = g_off[c] + sboff[c >> 8] + atomicSub(&g_cnt[c], 1) - 1;
        g_src[pos] = r;
    }
    // scale 16 h rows: h'[r] = h[r] * dinv[r]  (fp16 in place, coalesced)
    {
        __half2* H2 = (__half2*)g_h;
        int row0 = blockIdx.x * 16 + (t >> 7);   // 2 rows per pass
        int dd = t & 127;
#pragma unroll
        for (int rr = 0; rr < 16; rr += 2) {
            int row = row0 + rr;
            if (row < NN) {
                size_t i = ((size_t)row << 7) + dd;
                float w = g_dinv[row];
                float2 f = __half22float2(H2[i]);
                H2[i] = __floats2half2_rn(f.x * w, f.y * w);
            }
        }
    }
}

// ---------------- fused gather + bias + BN-stats (smem-staged, HADD2) ----------------
// out[c] = (h'[c] + sum_j h'[src_j]) * dinv[c] + bias
__global__ __launch_bounds__(128) void k_gather_bn(const float* __restrict__ bias,
                                                   float* __restrict__ out) {
    __shared__ unsigned sidx[128];   // staged (src << 7)
    const int d = threadIdx.x;
    const __half2* __restrict__ H2 = (const __half2*)g_h;
    const float2 bi = *(const float2*)&bias[2 * d];
    float s0 = 0.f, s1 = 0.f, q0 = 0.f, q1 = 0.f;
    const __half2 hzero = __floats2half2_rn(0.f, 0.f);

    for (int c = blockIdx.x; c < NN; c += gridDim.x) {
        const float dc = g_dinv[c];
        const int beg = g_off[c] + g_boff[c >> 8];
        const int end = (c + 1 < NN) ? g_off[c + 1] + g_boff[(c + 1) >> 8] : NE;

        float2 hs = __half22float2(__ldg(H2 + (((unsigned)c << 7) + d)));
        float a0 = hs.x, a1 = hs.y;   // self loop: h'[c]

        for (int base = beg; base < end; base += 128) {
            int n = end - base;
            if (n > 128) n = 128;
            if (d < n) sidx[d] = (unsigned)__ldg(&g_src[base + d]) << 7;
            __syncthreads();
            int k = 0;
            for (; k + 3 < n; k += 4) {
                __half2 v0 = __ldg(H2 + (sidx[k]     + d));
                __half2 v1 = __ldg(H2 + (sidx[k + 1] + d));
                __half2 v2 = __ldg(H2 + (sidx[k + 2] + d));
                __half2 v3 = __ldg(H2 + (sidx[k + 3] + d));
                __half2 p = __hadd2(__hadd2(v0, v1), __hadd2(v2, v3));
                float2 f = __half22float2(p);
                a0 += f.x; a1 += f.y;
            }
            if (k < n) {
                __half2 p = hzero;
                for (; k < n; k++) p = __hadd2(p, __ldg(H2 + (sidx[k] + d)));
                float2 f = __half22float2(p);
                a0 += f.x; a1 += f.y;
            }
            __syncthreads();
        }
        float o0 = fmaf(a0, dc, bi.x);
        float o1 = fmaf(a1, dc, bi.y);
        *(float2*)&out[(size_t)c * D + 2 * d] = make_float2(o0, o1);
        s0 += o0; s1 += o1;
        q0 = fmaf(o0, o0, q0); q1 = fmaf(o1, o1, q1);
    }
    atomicAdd(&g_bnstat[2 * d], s0);
    atomicAdd(&g_bnstat[2 * d + 1], s1);
    atomicAdd(&g_bnstat[D + 2 * d], q0);
    atomicAdd(&g_bnstat[D + 2 * d + 1], q1);
}

// ---------------- BN finalize ----------------
__global__ void k_bn_params(const float* __restrict__ gamma, const float* __restrict__ beta) {
    int d = threadIdx.x;
    float inv_n = 1.0f / (float)NN;
    float mean = g_bnstat[d] * inv_n;
    float var = g_bnstat[D + d] * inv_n - mean * mean;
    float a = gamma[d] * rsqrtf(var + BN_EPS);
    g_bn_a[d] = a;
    g_bn_b[d] = beta[d] - mean * a;
}

__global__ void k_bn_apply(float* __restrict__ out) {
    int idx = blockIdx.x * blockDim.x + threadIdx.x;
    if (idx >= NN * (D / 4)) return;
    int dq = (idx & 63) * 4;
    float4 a = *(const float4*)&g_bn_a[dq];
    float4 b = *(const float4*)&g_bn_b[dq];
    float4 v = ((const float4*)out)[idx];
    float4 o;
    o.x = fmaxf(fmaf(v.x, a.x, b.x), 0.f);
    o.y = fmaxf(fmaf(v.y, a.y, b.y), 0.f);
    o.z = fmaxf(fmaf(v.z, a.z, b.z), 0.f);
    o.w = fmaxf(fmaf(v.w, a.w, b.w), 0.f);
    ((float4*)out)[idx] = o;
}

// ---------------- launch ----------------
extern "C" void kernel_launch(void* const* d_in, const int* in_sizes, int n_in,
                              void* d_out, int out_size) {
    const float* x = (const float*)d_in[0];
    const int* ei = (const int*)d_in[1];
    const float* W = (const float*)d_in[2];
    const float* bias = (const float*)d_in[3];
    const float* gamma = (const float*)d_in[4];
    const float* beta = (const float*)d_in[5];
    float* out = (float*)d_out;

    __half* h;  cudaGetSymbolAddress((void**)&h, g_h);
    int* cnt;   cudaGetSymbolAddress((void**)&cnt, g_cnt);
    float* bns; cudaGetSymbolAddress((void**)&bns, g_bnstat);

    cudaMemsetAsync(cnt, 0, NN * sizeof(int));
    cudaMemsetAsync(bns, 0, 2 * D * sizeof(float));

    // 1: gemm (+edge count)   2: scan1   3: fill (+boff, +h scale)   4: gather (profiled)
    dim3 ggrid((NN + 127) / 128, D / 64);
    k_gemm_bf16<<<ggrid, 256>>>(x, W, h, ei);

    k_scan1<<<NSCB, 256>>>();
    k_fill<<<(NE + 255) / 256, 256>>>(ei);

    k_gather_bn<<<1480, 128>>>(bias, out);

    k_bn_params<<<1, 256>>>(gamma, beta);

    int q = NN * (D / 4);
    k_bn_apply<<<(q + 255) / 256, 256>>>(out);
}

// round 13
// speedup vs baseline: 1.8042x; 1.1170x over previous
#include <cuda_runtime.h>
#include <cuda_fp16.h>
#include <cstdint>

#define NN 50000
#define NE 800000
#define D  256
#define BN_EPS 1e-5f
#define NSCB 196   // ceil(NN/256) scan blocks

// ---------------- scratch (static device allocations) ----------------
__device__ __half g_h[NN * D];       // 25.6 MB: h, scaled to h*dinv in k_fill
__device__ float g_dinv[NN];
__device__ int   g_cnt[NN];
__device__ int   g_off[NN + 1];      // local-exclusive offsets (pre-boff)
__device__ int   g_src[NE];
__device__ int   g_bsum[NSCB];
__device__ int   g_boff[NSCB];       // published by k_fill block 0
__device__ float g_bnstat[2 * D];
__device__ float g_bn_a[D];
__device__ float g_bn_b[D];

// ---------------- multi-block scan helper ----------------
__device__ __forceinline__ int block_incl_scan256(int v, int tid) {
    __shared__ int ws[8];
    int lane = tid & 31, w = tid >> 5;
    int inc = v;
#pragma unroll
    for (int o = 1; o < 32; o <<= 1) {
        int n = __shfl_up_sync(0xFFFFFFFFu, inc, o);
        if (lane >= o) inc += n;
    }
    if (lane == 31) ws[w] = inc;
    __syncthreads();
    if (w == 0) {
        int s = (lane < 8) ? ws[lane] : 0;
#pragma unroll
        for (int o = 1; o < 8; o <<= 1) {
            int n = __shfl_up_sync(0xFFFFFFFFu, s, o);
            if (lane >= o) s += n;
        }
        if (lane < 8) ws[lane] = s;
    }
    __syncthreads();
    return inc + (w > 0 ? ws[w - 1] : 0);
}

// ---------------- GEMM (+fused edge count): H(fp16) = X @ W^T ----------------
#define GPAD 20
#define EPB 512

__device__ __forceinline__ unsigned pack_bf16x2(float k0, float k1) {
    unsigned r;
    asm("cvt.rn.bf16x2.f32 %0, %1, %2;" : "=r"(r) : "f"(k1), "f"(k0));
    return r;
}

#define MMA_BF16(acc, a, b) \
    asm volatile("mma.sync.aligned.m16n8k16.row.col.f32.bf16.bf16.f32 " \
                 "{%0,%1,%2,%3},{%4,%5,%6,%7},{%8,%9},{%0,%1,%2,%3};" \
                 : "+f"(acc[0]), "+f"(acc[1]), "+f"(acc[2]), "+f"(acc[3]) \
                 : "r"(a[0]), "r"(a[1]), "r"(a[2]), "r"(a[3]), "r"(b[0]), "r"(b[1]))

#define LDSM4(r, addr) \
    asm volatile("ldmatrix.sync.aligned.m8n8.x4.shared.b16 {%0,%1,%2,%3}, [%4];" \
                 : "=r"(r[0]), "=r"(r[1]), "=r"(r[2]), "=r"(r[3]) : "r"(addr))

__device__ __forceinline__ void split2(float a, float b, unsigned& hi, unsigned& lo) {
    hi = __byte_perm(__float_as_uint(a), __float_as_uint(b), 0x7632);
    float la = a - __uint_as_float(hi << 16);
    float lb = b - __uint_as_float(hi & 0xFFFF0000u);
    lo = pack_bf16x2(la, lb);
}

__global__ __launch_bounds__(256) void k_gemm_bf16(const float* __restrict__ X,
                                                   const float* __restrict__ W,
                                                   __half* __restrict__ H,
                                                   const int* __restrict__ ei) {
    // fused edge-degree count: this block's slice
    {
        int bid = blockIdx.y * gridDim.x + blockIdx.x;
        int e0 = bid * EPB;
#pragma unroll
        for (int p = 0; p < 2; p++) {
            int e = e0 + threadIdx.x + p * 256;
            if (e < NE && e < e0 + EPB) atomicAdd(&g_cnt[ei[NE + e]], 1);
        }
    }

    __shared__ unsigned Ahi[128][GPAD], Alo[128][GPAD];
    __shared__ unsigned Bhi[64][GPAD],  Blo[64][GPAD];

    const int bm = blockIdx.x * 128;
    const int bn = blockIdx.y * 64;
    const int tid = threadIdx.x;
    const int warp = tid >> 5, lane = tid & 31;
    const int wm = warp & 3, wn = warp >> 2;
    const int grp = lane >> 2, tig = lane & 3;

    const int lr = lane & 7, sel = lane >> 3;
    const int a_row = ((sel & 1) ? 8 : 0) + lr;
    const int a_col = (sel & 2) ? 4 : 0;
    const int b_row = ((sel & 2) ? 8 : 0) + lr;
    const int b_col = (sel & 1) ? 4 : 0;

    const uint32_t sAhi = (uint32_t)__cvta_generic_to_shared(&Ahi[0][0]);
    const uint32_t sAlo = (uint32_t)__cvta_generic_to_shared(&Alo[0][0]);
    const uint32_t sBhi = (uint32_t)__cvta_generic_to_shared(&Bhi[0][0]);
    const uint32_t sBlo = (uint32_t)__cvta_generic_to_shared(&Blo[0][0]);

    float acc[2][4][4];
#pragma unroll
    for (int mi = 0; mi < 2; mi++)
#pragma unroll
        for (int ni = 0; ni < 4; ni++)
#pragma unroll
            for (int q = 0; q < 4; q++) acc[mi][ni][q] = 0.0f;

    for (int k0 = 0; k0 < D; k0 += 32) {
#pragma unroll
        for (int p = 0; p < 4; p++) {
            int f = tid + p * 256;
            int row = f >> 3;
            int q = f & 7;
            float4 v = make_float4(0.f, 0.f, 0.f, 0.f);
            int gr = bm + row;
            if (gr < NN) v = *(const float4*)&X[(size_t)gr * D + k0 + q * 4];
            unsigned h0, l0, h1, l1;
            split2(v.x, v.y, h0, l0);
            split2(v.z, v.w, h1, l1);
            Ahi[row][q * 2]     = h0;
            Ahi[row][q * 2 + 1] = h1;
            Alo[row][q * 2]     = l0;
            Alo[row][q * 2 + 1] = l1;
        }
#pragma unroll
        for (int p = 0; p < 2; p++) {
            int f = tid + p * 256;
            int row = f >> 3;
            int q = f & 7;
            float4 v = *(const float4*)&W[(size_t)(bn + row) * D + k0 + q * 4];
            unsigned h0, l0, h1, l1;
            split2(v.x, v.y, h0, l0);
            split2(v.z, v.w, h1, l1);
            Bhi[row][q * 2]     = h0;
            Bhi[row][q * 2 + 1] = h1;
            Blo[row][q * 2]     = l0;
            Blo[row][q * 2 + 1] = l1;
        }
        __syncthreads();

#pragma unroll
        for (int ks = 0; ks < 16; ks += 8) {
            unsigned ah[2][4], al[2][4], bh[2][4], bl[2][4];
#pragma unroll
            for (int mi = 0; mi < 2; mi++) {
                uint32_t off = (uint32_t)(((wm * 32 + mi * 16 + a_row) * GPAD + ks + a_col) << 2);
                LDSM4(ah[mi], sAhi + off);
                LDSM4(al[mi], sAlo + off);
            }
#pragma unroll
            for (int p = 0; p < 2; p++) {
                uint32_t off = (uint32_t)(((wn * 32 + p * 16 + b_row) * GPAD + ks + b_col) << 2);
                LDSM4(bh[p], sBhi + off);
                LDSM4(bl[p], sBlo + off);
            }
#pragma unroll
            for (int mi = 0; mi < 2; mi++)
#pragma unroll
                for (int ni = 0; ni < 4; ni++) {
                    int p = ni >> 1, o = (ni & 1) * 2;
                    MMA_BF16(acc[mi][ni], ah[mi], (&bh[p][o]));
                    MMA_BF16(acc[mi][ni], ah[mi], (&bl[p][o]));
                    MMA_BF16(acc[mi][ni], al[mi], (&bh[p][o]));
                }
        }
        __syncthreads();
    }

#pragma unroll
    for (int mi = 0; mi < 2; mi++)
#pragma unroll
        for (int ni = 0; ni < 4; ni++) {
            int r0 = bm + wm * 32 + mi * 16 + grp;
            int c0 = bn + wn * 32 + ni * 8 + tig * 2;
            if (r0 < NN)
                *(__half2*)&H[(size_t)r0 * D + c0] = __floats2half2_rn(acc[mi][ni][0], acc[mi][ni][1]);
            if (r0 + 8 < NN)
                *(__half2*)&H[(size_t)(r0 + 8) * D + c0] = __floats2half2_rn(acc[mi][ni][2], acc[mi][ni][3]);
        }
}

// ---------------- scan phase 1 + dinv ----------------
__global__ __launch_bounds__(256) void k_scan1(void) {
    int tid = threadIdx.x;
    int idx = blockIdx.x * 256 + tid;
    int v = (idx < NN) ? g_cnt[idx] : 0;
    if (idx < NN) g_dinv[idx] = rsqrtf((float)(v + 1));
    int inc = block_incl_scan256(v, tid);
    if (idx < NN) g_off[idx] = inc - v;
    if (tid == 255) g_bsum[blockIdx.x] = inc;
}

// ---------------- fill CSR (+inline block scan, +h *= dinv scaling) ----------------
__global__ __launch_bounds__(256) void k_fill(const int* __restrict__ ei) {
    __shared__ int sboff[NSCB];
    int t = threadIdx.x;
    {
        int v = (t < NSCB) ? g_bsum[t] : 0;
        int inc = block_incl_scan256(v, t);
        if (t < NSCB) {
            sboff[t] = inc - v;
            if (blockIdx.x == 0) g_boff[t] = inc - v;
        }
    }
    __syncthreads();
    int e = blockIdx.x * 256 + t;
    if (e < NE) {
        int r = ei[e];
        int c = ei[NE + e];
        int pos = g_off[c] + sboff[c >> 8] + atomicSub(&g_cnt[c], 1) - 1;
        g_src[pos] = r;
    }
    // scale 16 h rows: h'[r] = h[r] * dinv[r]
    {
        __half2* H2 = (__half2*)g_h;
        int row0 = blockIdx.x * 16 + (t >> 7);
        int dd = t & 127;
#pragma unroll
        for (int rr = 0; rr < 16; rr += 2) {
            int row = row0 + rr;
            if (row < NN) {
                size_t i = ((size_t)row << 7) + dd;
                float w = g_dinv[row];
                float2 f = __half22float2(H2[i]);
                H2[i] = __floats2half2_rn(f.x * w, f.y * w);
            }
        }
    }
}

// ---------------- warp-per-node gather + bias + BN-stats ----------------
// One warp per node; lane owns cols [lane*8, lane*8+8) = one uint4 (4 half2).
__device__ __forceinline__ uint4 hadd4(uint4 a, uint4 b) {
    uint4 r;
    *(__half2*)&r.x = __hadd2(*(const __half2*)&a.x, *(const __half2*)&b.x);
    *(__half2*)&r.y = __hadd2(*(const __half2*)&a.y, *(const __half2*)&b.y);
    *(__half2*)&r.z = __hadd2(*(const __half2*)&a.z, *(const __half2*)&b.z);
    *(__half2*)&r.w = __hadd2(*(const __half2*)&a.w, *(const __half2*)&b.w);
    return r;
}

__device__ __forceinline__ void acc8(float* a, uint4 u) {
    float2 f0 = __half22float2(*(const __half2*)&u.x);
    float2 f1 = __half22float2(*(const __half2*)&u.y);
    float2 f2 = __half22float2(*(const __half2*)&u.z);
    float2 f3 = __half22float2(*(const __half2*)&u.w);
    a[0] += f0.x; a[1] += f0.y; a[2] += f1.x; a[3] += f1.y;
    a[4] += f2.x; a[5] += f2.y; a[6] += f3.x; a[7] += f3.y;
}

__global__ __launch_bounds__(256) void k_gather_bn(const float* __restrict__ bias,
                                                   float* __restrict__ out) {
    const int lane = threadIdx.x & 31;
    const int wglob = (blockIdx.x * 256 + threadIdx.x) >> 5;
    const int nwarps = (gridDim.x * 256) >> 5;
    const uint4* __restrict__ H4 = (const uint4*)g_h;   // 32 uint4 per row

    const float4 b0 = *(const float4*)&bias[lane * 8];
    const float4 b1 = *(const float4*)&bias[lane * 8 + 4];
    float s[8], q[8];
#pragma unroll
    for (int i = 0; i < 8; i++) { s[i] = 0.f; q[i] = 0.f; }

    for (int c = wglob; c < NN; c += nwarps) {
        const float dc = g_dinv[c];
        const int beg = __ldg(&g_off[c]) + __ldg(&g_boff[c >> 8]);
        const int end = (c + 1 < NN) ? __ldg(&g_off[c + 1]) + __ldg(&g_boff[(c + 1) >> 8]) : NE;

        float a[8];
#pragma unroll
        for (int i = 0; i < 8; i++) a[i] = 0.f;
        acc8(a, __ldg(H4 + ((unsigned)c * 32u + lane)));   // self loop (h' already scaled)

        int j = beg;
        for (; j + 3 < end; j += 4) {
            int r0 = __ldg(&g_src[j]);
            int r1 = __ldg(&g_src[j + 1]);
            int r2 = __ldg(&g_src[j + 2]);
            int r3 = __ldg(&g_src[j + 3]);
            uint4 v0 = __ldg(H4 + ((unsigned)r0 * 32u + lane));
            uint4 v1 = __ldg(H4 + ((unsigned)r1 * 32u + lane));
            uint4 v2 = __ldg(H4 + ((unsigned)r2 * 32u + lane));
            uint4 v3 = __ldg(H4 + ((unsigned)r3 * 32u + lane));
            acc8(a, hadd4(hadd4(v0, v1), hadd4(v2, v3)));
        }
        for (; j < end; j++) {
            int r = __ldg(&g_src[j]);
            acc8(a, __ldg(H4 + ((unsigned)r * 32u + lane)));
        }

        float o[8];
        o[0] = fmaf(a[0], dc, b0.x); o[1] = fmaf(a[1], dc, b0.y);
        o[2] = fmaf(a[2], dc, b0.z); o[3] = fmaf(a[3], dc, b0.w);
        o[4] = fmaf(a[4], dc, b1.x); o[5] = fmaf(a[5], dc, b1.y);
        o[6] = fmaf(a[6], dc, b1.z); o[7] = fmaf(a[7], dc, b1.w);
        float* op = &out[(size_t)c * D + lane * 8];
        *(float4*)op       = make_float4(o[0], o[1], o[2], o[3]);
        *(float4*)(op + 4) = make_float4(o[4], o[5], o[6], o[7]);
#pragma unroll
        for (int i = 0; i < 8; i++) {
            s[i] += o[i];
            q[i] = fmaf(o[i], o[i], q[i]);
        }
    }

    // block-level reduction of BN stats, then 512 global atomics per block
    __shared__ float sred[2 * D];
    for (int i = threadIdx.x; i < 2 * D; i += 256) sred[i] = 0.f;
    __syncthreads();
#pragma unroll
    for (int i = 0; i < 8; i++) {
        atomicAdd(&sred[lane * 8 + i], s[i]);
        atomicAdd(&sred[D + lane * 8 + i], q[i]);
    }
    __syncthreads();
    atomicAdd(&g_bnstat[threadIdx.x], sred[threadIdx.x]);
    atomicAdd(&g_bnstat[D + threadIdx.x], sred[D + threadIdx.x]);
}

// ---------------- BN finalize ----------------
__global__ void k_bn_params(const float* __restrict__ gamma, const float* __restrict__ beta) {
    int d = threadIdx.x;
    float inv_n = 1.0f / (float)NN;
    float mean = g_bnstat[d] * inv_n;
    float var = g_bnstat[D + d] * inv_n - mean * mean;
    float a = gamma[d] * rsqrtf(var + BN_EPS);
    g_bn_a[d] = a;
    g_bn_b[d] = beta[d] - mean * a;
}

__global__ void k_bn_apply(float* __restrict__ out) {
    int idx = blockIdx.x * blockDim.x + threadIdx.x;
    if (idx >= NN * (D / 4)) return;
    int dq = (idx & 63) * 4;
    float4 a = *(const float4*)&g_bn_a[dq];
    float4 b = *(const float4*)&g_bn_b[dq];
    float4 v = ((const float4*)out)[idx];
    float4 o;
    o.x = fmaxf(fmaf(v.x, a.x, b.x), 0.f);
    o.y = fmaxf(fmaf(v.y, a.y, b.y), 0.f);
    o.z = fmaxf(fmaf(v.z, a.z, b.z), 0.f);
    o.w = fmaxf(fmaf(v.w, a.w, b.w), 0.f);
    ((float4*)out)[idx] = o;
}

// ---------------- launch ----------------
extern "C" void kernel_launch(void* const* d_in, const int* in_sizes, int n_in,
                              void* d_out, int out_size) {
    const float* x = (const float*)d_in[0];
    const int* ei = (const int*)d_in[1];
    const float* W = (const float*)d_in[2];
    const float* bias = (const float*)d_in[3];
    const float* gamma = (const float*)d_in[4];
    const float* beta = (const float*)d_in[5];
    float* out = (float*)d_out;

    __half* h;  cudaGetSymbolAddress((void**)&h, g_h);
    int* cnt;   cudaGetSymbolAddress((void**)&cnt, g_cnt);
    float* bns; cudaGetSymbolAddress((void**)&bns, g_bnstat);

    cudaMemsetAsync(cnt, 0, NN * sizeof(int));
    cudaMemsetAsync(bns, 0, 2 * D * sizeof(float));

    // 1: gemm (+edge count)   2: scan1   3: fill (+boff, +h scale)   4: gather (profiled)
    dim3 ggrid((NN + 127) / 128, D / 64);
    k_gemm_bf16<<<ggrid, 256>>>(x, W, h, ei);

    k_scan1<<<NSCB, 256>>>();
    k_fill<<<(NE + 255) / 256, 256>>>(ei);

    k_gather_bn<<<1480, 256>>>(bias, out);

    k_bn_params<<<1, 256>>>(gamma, beta);

    int q = NN * (D / 4);
    k_bn_apply<<<(q + 255) / 256, 256>>>(out);
}